// round 16
// baseline (speedup 1.0000x reference)
#include <cuda_runtime.h>
#include <cuda_fp16.h>
#include <stdint.h>

// ---------------- problem constants ----------------
#define TOT_E      10
#define SPIKE_E0   8
#define DIN        512
#define DHID       1024
#define DOUT       256
#define BTOK       32768
#define TSPK       16
#define NPAIRS     (BTOK * 2)
#define BM 128
#define BN 128
#define BKH 32                             // K halves per slab
#define MAX_TILES  (NPAIRS / BM + TOT_E)   // 522
#define SROW 40                            // smem row stride in halves (80 B)
#define SROWB (SROW * 2)                   // 80 bytes

// ---------------- device scratch (device-code references only) ------------
__device__ __half g_h[(size_t)NPAIRS * DHID];
__device__ __half g_xh[(size_t)BTOK * DIN];
__device__ __half g_W1t[(size_t)TOT_E * DIN * DHID];   // [E][N=DHID][K=DIN]
__device__ __half g_W2t[(size_t)TOT_E * DHID * DOUT];  // [E][N=DOUT][K=DHID]
__device__ int    g_perm[NPAIRS];
__device__ float  g_wgt[NPAIRS];
__device__ int    g_topk_e[NPAIRS];
__device__ float  g_topk_w[NPAIRS];
__device__ int    g_counts[TOT_E];
__device__ int    g_cursor[TOT_E];         // zero-based allocation cursor
__device__ int    g_tile_e[MAX_TILES];
__device__ int    g_tile_r0[MAX_TILES];
__device__ int    g_tile_r1[MAX_TILES];
__device__ int    g_num_tiles;

// ---------------- helpers ----------------
__device__ __forceinline__ void mma_f16(float* c, const uint32_t* a, const uint32_t* b) {
    asm volatile(
        "mma.sync.aligned.m16n8k16.row.col.f32.f16.f16.f32 "
        "{%0,%1,%2,%3}, {%4,%5,%6,%7}, {%8,%9}, {%0,%1,%2,%3};"
        : "+f"(c[0]), "+f"(c[1]), "+f"(c[2]), "+f"(c[3])
        : "r"(a[0]), "r"(a[1]), "r"(a[2]), "r"(a[3]),
          "r"(b[0]), "r"(b[1]));
}
__device__ __forceinline__ void ldsm_x4(uint32_t& r0, uint32_t& r1, uint32_t& r2,
                                        uint32_t& r3, uint32_t addr) {
    asm volatile("ldmatrix.sync.aligned.m8n8.x4.shared.b16 {%0,%1,%2,%3}, [%4];"
                 : "=r"(r0), "=r"(r1), "=r"(r2), "=r"(r3) : "r"(addr));
}
__device__ __forceinline__ uint32_t smem_u32(const void* p) {
    return (uint32_t)__cvta_generic_to_shared(p);
}
__device__ __forceinline__ void cp16(uint32_t dst, const void* src, int sz) {
    asm volatile("cp.async.cg.shared.global [%0], [%1], 16, %2;"
                 :: "r"(dst), "l"(src), "r"(sz));
}
__device__ __forceinline__ void cp_commit() {
    asm volatile("cp.async.commit_group;");
}
__device__ __forceinline__ void cp_wait0() {
    asm volatile("cp.async.wait_group 0;");
}
__device__ __forceinline__ void red_add_f32(float* addr, float v) {
    asm volatile("red.global.add.f32 [%0], %1;" :: "l"(addr), "f"(v) : "memory");
}

// ---------------- small kernels ----------------
__global__ void zero_counts_kernel() {
    if (threadIdx.x < TOT_E) {
        g_counts[threadIdx.x] = 0;
        g_cursor[threadIdx.x] = 0;
    }
}
__global__ void zero_out_kernel(float4* __restrict__ out) {
    int i = blockIdx.x * blockDim.x + threadIdx.x;   // over BTOK*DOUT/4
    out[i] = make_float4(0.f, 0.f, 0.f, 0.f);
}

// Router: one warp per token
__global__ void router_kernel(const float* __restrict__ x,
                              const float* __restrict__ spike,
                              const float* __restrict__ Wr,
                              const float* __restrict__ br) {
    int warp = (blockIdx.x * blockDim.x + threadIdx.x) >> 5;
    int lane = threadIdx.x & 31;
    if (warp >= BTOK) return;
    const float* xr = x + (size_t)warp * DIN;

    float acc[TOT_E];
#pragma unroll
    for (int e = 0; e < TOT_E; e++) acc[e] = 0.f;
    for (int k = lane; k < DIN; k += 32) {
        float xv = xr[k];
        const float* wrow = Wr + k * TOT_E;
#pragma unroll
        for (int e = 0; e < TOT_E; e++) acc[e] += xv * wrow[e];
    }
#pragma unroll
    for (int e = 0; e < TOT_E; e++)
#pragma unroll
        for (int off = 16; off; off >>= 1)
            acc[e] += __shfl_xor_sync(0xffffffffu, acc[e], off);
    float sp = (lane < TSPK) ? spike[warp * TSPK + lane] : 0.f;
#pragma unroll
    for (int off = 16; off; off >>= 1)
        sp += __shfl_xor_sync(0xffffffffu, sp, off);

    if (lane == 0) {
        float avg = sp * (1.f / TSPK);
        float lg[TOT_E];
#pragma unroll
        for (int e = 0; e < TOT_E; e++)
            lg[e] = acc[e] + br[e] + (e >= SPIKE_E0 ? avg : 0.f);
        float m = lg[0];
#pragma unroll
        for (int e = 1; e < TOT_E; e++) m = fmaxf(m, lg[e]);
        float p[TOT_E]; float Z = 0.f;
#pragma unroll
        for (int e = 0; e < TOT_E; e++) { p[e] = expf(lg[e] - m); Z += p[e]; }
        float invZ = 1.f / Z;
#pragma unroll
        for (int e = 0; e < TOT_E; e++) p[e] *= invZ;
        int e0 = 0;
#pragma unroll
        for (int e = 1; e < TOT_E; e++) if (p[e] > p[e0]) e0 = e;
        int e1 = (e0 == 0) ? 1 : 0;
#pragma unroll
        for (int e = 0; e < TOT_E; e++)
            if (e != e0 && p[e] > p[e1]) e1 = e;
        float s = p[e0] + p[e1] + 1e-9f;
        g_topk_e[2 * warp + 0] = e0;
        g_topk_e[2 * warp + 1] = e1;
        g_topk_w[2 * warp + 0] = p[e0] / s;
        g_topk_w[2 * warp + 1] = p[e1] / s;
        atomicAdd(&g_counts[e0], 1);
        atomicAdd(&g_counts[e1], 1);
    }
}

// Tile-table build only (off the spine; runs on s1 after router)
__global__ void tiles_kernel() {
    __shared__ int cnts[TOT_E];
    int tid = threadIdx.x;
    if (tid < TOT_E) cnts[tid] = g_counts[tid];
    __syncthreads();
    if (tid < TOT_E) {
        int roff = 0, toff = 0;
        for (int i = 0; i < tid; i++) {
            roff += cnts[i];
            toff += (cnts[i] + BM - 1) / BM;
        }
        int n = cnts[tid];
        for (int t = 0; t < n; t += BM) {
            g_tile_e[toff]  = tid;
            g_tile_r0[toff] = roff + t;
            int r1 = roff + t + BM;
            int re = roff + n;
            g_tile_r1[toff] = r1 < re ? r1 : re;
            toff++;
        }
        if (tid == TOT_E - 1) g_num_tiles = toff;
    }
}

// Scatter: self-sufficient (local expert prefix + zero-based cursor)
__global__ void scatter_kernel() {
    __shared__ int cnt[TOT_E];
    __shared__ int base[TOT_E];
    __shared__ int offs[TOT_E];
    int tid = threadIdx.x;
    if (tid < TOT_E) {
        cnt[tid] = 0;
        // expert start offset = prefix sum of final counts (router done)
        int o = 0;
        for (int i = 0; i < tid; i++) o += g_counts[i];
        offs[tid] = o;
    }
    __syncthreads();
    int i = blockIdx.x * blockDim.x + tid;
    int e = g_topk_e[i];
    int loc = atomicAdd(&cnt[e], 1);
    __syncthreads();
    if (tid < TOT_E) base[tid] = offs[tid] + atomicAdd(&g_cursor[tid], cnt[tid]);
    __syncthreads();
    int pos = base[e] + loc;
    g_perm[pos] = i >> 1;
    g_wgt[pos]  = g_topk_w[i];
}

// x (fp32) -> g_xh (half), fully coalesced
__global__ void cvtx_kernel(const float4* __restrict__ x) {
    int i = blockIdx.x * blockDim.x + threadIdx.x;
    float4 v = x[i];
    ((__half2*)g_xh)[2 * i]     = __floats2half2_rn(v.x, v.y);
    ((__half2*)g_xh)[2 * i + 1] = __floats2half2_rn(v.z, v.w);
}

// W[e][K][N] fp32 -> Wt[e][N][K] half
template<bool FIRST>
__global__ void transpose_kernel(const float* __restrict__ W, int K, int N) {
    __half* Wt = FIRST ? g_W1t : g_W2t;
    __shared__ float t[32][33];
    int e = blockIdx.z;
    const float* Ws = W + (size_t)e * K * N;
    __half* Wd = Wt + (size_t)e * K * N;
    int k0 = blockIdx.x * 32, n0 = blockIdx.y * 32;
    int tx = threadIdx.x, ty = threadIdx.y;   // 32 x 8
#pragma unroll
    for (int i = 0; i < 32; i += 8)
        t[ty + i][tx] = Ws[(size_t)(k0 + ty + i) * N + n0 + tx];
    __syncthreads();
#pragma unroll
    for (int i = 0; i < 32; i += 8)
        Wd[(size_t)(n0 + ty + i) * K + k0 + tx] = __float2half_rn(t[tx][ty + i]);
}

// ---------------- fp16 grouped GEMM: 2-stage cp.async + ldmatrix -----------
// BM=128 BN=128 BKH=32, 8 warps (2x4), warp tile 64x32, mma.m16n8k16, occ 2
template<bool FIRST>
__global__ __launch_bounds__(256, 2)
void gemm_kernel(const float* __restrict__ bias, float* __restrict__ out) {
    const int KDIM = FIRST ? DIN : DHID;
    const int NDIM = FIRST ? DHID : DOUT;
    const __half* A0 = FIRST ? g_xh : g_h;
    const __half* Bt = FIRST ? g_W1t : g_W2t;

    __shared__ __half As[2][BM][SROW];
    __shared__ __half Bs[2][BN][SROW];

    int bt = blockIdx.x;
    if (bt >= g_num_tiles) return;
    int e  = g_tile_e[bt];
    int r0 = g_tile_r0[bt];
    int r1 = g_tile_r1[bt];
    int n0 = blockIdx.y * BN;

    const __half* Bexp = Bt + (size_t)e * NDIM * KDIM;

    int tid  = threadIdx.x;
    int lane = tid & 31;
    int wid  = tid >> 5;
    int gidl = lane >> 2;
    int tg   = lane & 3;
    int wm   = (wid >> 2) * 64;
    int wn   = (wid & 3) * 32;

    // staging: 2 threads per row, each 16 halves (two 16B cp.async)
    int srow = tid >> 1;
    int scol = (tid & 1) * 16;
    int ra = r0 + srow;
    bool av = ra < r1;
    const __half* aRow;
    if (FIRST) aRow = A0 + (av ? (size_t)g_perm[ra] * KDIM : 0) + scol;
    else       aRow = A0 + (av ? (size_t)ra * KDIM : 0) + scol;
    const __half* bRow = Bexp + (size_t)(n0 + srow) * KDIM + scol;
    int asz = av ? 16 : 0;
    uint32_t aDst0 = smem_u32(&As[0][srow][scol]);
    uint32_t bDst0 = smem_u32(&Bs[0][srow][scol]);
    const uint32_t A_STAGE_B = (uint32_t)(BM * SROWB);
    const uint32_t B_STAGE_B = (uint32_t)(BN * SROWB);

    // ldmatrix lane-address bases (stage 0)
    uint32_t aLdBase = smem_u32(&As[0][0][0])
                     + (uint32_t)(wm + (lane & 15)) * SROWB
                     + (uint32_t)(lane >> 4) * 16;
    uint32_t bLdBase = smem_u32(&Bs[0][0][0])
                     + (uint32_t)(wn + (lane & 7) + ((lane >> 4) & 1) * 8) * SROWB
                     + (uint32_t)((lane >> 3) & 1) * 16;

    float acc[4][4][4];
#pragma unroll
    for (int a = 0; a < 4; a++)
#pragma unroll
        for (int b = 0; b < 4; b++)
#pragma unroll
            for (int c = 0; c < 4; c++) acc[a][b][c] = 0.f;

    const int NC = KDIM / BKH;

    // ---- prologue: stage slab 0 ----
    {
        cp16(aDst0,      aRow,     asz);
        cp16(aDst0 + 16, aRow + 8, asz);
        cp16(bDst0,      bRow,     16);
        cp16(bDst0 + 16, bRow + 8, 16);
        cp_commit();
    }

    for (int c = 0; c < NC; c++) {
        cp_wait0();
        __syncthreads();
        int cur = c & 1;

        // prefetch slab c+1
        if (c + 1 < NC) {
            int nxt = (c + 1) & 1;
            const __half* as = aRow + (c + 1) * BKH;
            const __half* bs = bRow + (c + 1) * BKH;
            uint32_t ad = aDst0 + nxt * A_STAGE_B;
            uint32_t bd = bDst0 + nxt * B_STAGE_B;
            cp16(ad,      as,     asz);
            cp16(ad + 16, as + 8, asz);
            cp16(bd,      bs,     16);
            cp16(bd + 16, bs + 8, 16);
            cp_commit();
        }

        // ---- compute slab c: two k16 steps ----
        uint32_t aB = aLdBase + (uint32_t)cur * A_STAGE_B;
        uint32_t bB = bLdBase + (uint32_t)cur * B_STAGE_B;
#pragma unroll
        for (int kk = 0; kk < 2; kk++) {
            uint32_t kB = (uint32_t)kk * 32;
            uint32_t af[4][4], bf4[2][4];
#pragma unroll
            for (int mi = 0; mi < 4; mi++)
                ldsm_x4(af[mi][0], af[mi][1], af[mi][2], af[mi][3],
                        aB + kB + (uint32_t)mi * (16 * SROWB));
#pragma unroll
            for (int nj = 0; nj < 2; nj++)
                ldsm_x4(bf4[nj][0], bf4[nj][1], bf4[nj][2], bf4[nj][3],
                        bB + kB + (uint32_t)nj * (16 * SROWB));
#pragma unroll
            for (int mi = 0; mi < 4; mi++)
#pragma unroll
                for (int ni = 0; ni < 4; ni++)
                    mma_f16(acc[mi][ni], af[mi], &bf4[ni >> 1][(ni & 1) * 2]);
        }
        __syncthreads();
    }

    // ---- epilogue ----
    const float* be = bias + (size_t)e * NDIM;
#pragma unroll
    for (int mi = 0; mi < 4; mi++) {
#pragma unroll
        for (int ri = 0; ri < 2; ri++) {
            int r = r0 + wm + mi * 16 + gidl + ri * 8;
            if (r >= r1) continue;
            if (FIRST) {
#pragma unroll
                for (int ni = 0; ni < 4; ni++) {
                    int cc = n0 + wn + ni * 8 + 2 * tg;
                    float v0 = fmaxf(acc[mi][ni][ri * 2 + 0] + be[cc],     0.f);
                    float v1 = fmaxf(acc[mi][ni][ri * 2 + 1] + be[cc + 1], 0.f);
                    *reinterpret_cast<__half2*>(g_h + (size_t)r * NDIM + cc) =
                        __floats2half2_rn(v0, v1);
                }
            } else {
                float sc = g_wgt[r];
                int token = g_perm[r];
                float* orow = out + (size_t)token * NDIM;
#pragma unroll
                for (int ni = 0; ni < 4; ni++) {
                    int cc = n0 + wn + ni * 8 + 2 * tg;
                    float v0 = (acc[mi][ni][ri * 2 + 0] + be[cc])     * sc;
                    float v1 = (acc[mi][ni][ri * 2 + 1] + be[cc + 1]) * sc;
                    red_add_f32(orow + cc,     v0);
                    red_add_f32(orow + cc + 1, v1);
                }
            }
        }
    }
}

// ---------------- launch: multi-stream DAG (capture-safe fork/join) -------
extern "C" void kernel_launch(void* const* d_in, const int* in_sizes, int n_in,
                              void* d_out, int out_size) {
    const float* x     = (const float*)d_in[0];
    const float* spike = (const float*)d_in[1];
    const float* Wr    = (const float*)d_in[2];
    const float* br    = (const float*)d_in[3];
    const float* W1    = (const float*)d_in[4];
    const float* b1    = (const float*)d_in[5];
    const float* W2    = (const float*)d_in[6];
    const float* b2    = (const float*)d_in[7];
    float* out = (float*)d_out;

    static cudaStream_t s1 = nullptr, s2 = nullptr;
    static cudaEvent_t evFork = nullptr, evR = nullptr, evA = nullptr, evB = nullptr;
    if (s1 == nullptr) {
        cudaStreamCreateWithFlags(&s1, cudaStreamNonBlocking);
        cudaStreamCreateWithFlags(&s2, cudaStreamNonBlocking);
        cudaEventCreateWithFlags(&evFork, cudaEventDisableTiming);
        cudaEventCreateWithFlags(&evR, cudaEventDisableTiming);
        cudaEventCreateWithFlags(&evA, cudaEventDisableTiming);
        cudaEventCreateWithFlags(&evB, cudaEventDisableTiming);
    }

    // fork
    cudaEventRecord(evFork, 0);
    cudaStreamWaitEvent(s1, evFork, 0);
    cudaStreamWaitEvent(s2, evFork, 0);

    // s2: inputs GEMM2 needs (W2 transpose, output zero-fill)
    transpose_kernel<false><<<dim3(DHID / 32, DOUT / 32, TOT_E), dim3(32, 8), 0, s2>>>(W2, DHID, DOUT);
    zero_out_kernel<<<(BTOK * DOUT / 4) / 256, 256, 0, s2>>>((float4*)out);
    cudaEventRecord(evB, s2);

    // main spine: routing
    zero_counts_kernel<<<1, 32>>>();
    router_kernel<<<BTOK / 8, 256>>>(x, spike, Wr, br);
    cudaEventRecord(evR, 0);
    scatter_kernel<<<NPAIRS / 256, 256>>>();

    // s1: inputs GEMM1 needs (x->half, W1 transpose, tile table after router)
    cvtx_kernel<<<(BTOK * DIN / 4) / 256, 256, 0, s1>>>((const float4*)x);
    transpose_kernel<true><<<dim3(DIN / 32, DHID / 32, TOT_E), dim3(32, 8), 0, s1>>>(W1, DIN, DHID);
    cudaStreamWaitEvent(s1, evR, 0);
    tiles_kernel<<<1, 32, 0, s1>>>();
    cudaEventRecord(evA, s1);

    // join s1 -> GEMM1
    cudaStreamWaitEvent(0, evA, 0);
    gemm_kernel<true><<<dim3(MAX_TILES, DHID / BN), 256>>>(b1, nullptr);

    // join s2 -> GEMM2 (fused combine via red.global.add into out)
    cudaStreamWaitEvent(0, evB, 0);
    gemm_kernel<false><<<dim3(MAX_TILES, DOUT / BN), 256>>>(b2, out);
}

// round 17
// speedup vs baseline: 1.0210x; 1.0210x over previous
#include <cuda_runtime.h>
#include <cuda_fp16.h>
#include <stdint.h>

// ---------------- problem constants ----------------
#define TOT_E      10
#define SPIKE_E0   8
#define DIN        512
#define DHID       1024
#define DOUT       256
#define BTOK       32768
#define TSPK       16
#define NPAIRS     (BTOK * 2)
#define BM 128
#define BN 128
#define BKH 32                             // K halves per slab
#define MAX_TILES  (NPAIRS / BM + TOT_E)   // 522
#define SROW 40                            // smem row stride in halves (80 B)
#define SROWB (SROW * 2)                   // 80 bytes

// ---------------- device scratch (device-code references only) ------------
__device__ __half g_h[(size_t)NPAIRS * DHID];
__device__ __half g_xh[(size_t)BTOK * DIN];
__device__ __half g_W1t[(size_t)TOT_E * DIN * DHID];   // [E][N=DHID][K=DIN]
__device__ __half g_W2t[(size_t)TOT_E * DHID * DOUT];  // [E][N=DOUT][K=DHID]
__device__ float  g_Wrt[TOT_E * DIN];                  // router W transposed [E][K]
__device__ int    g_perm[NPAIRS];
__device__ float  g_wgt[NPAIRS];
__device__ int    g_topk_e[NPAIRS];
__device__ float  g_topk_w[NPAIRS];
__device__ int    g_counts[TOT_E];
__device__ int    g_cursor[TOT_E];
__device__ int    g_tile_e[MAX_TILES];
__device__ int    g_tile_r0[MAX_TILES];
__device__ int    g_tile_r1[MAX_TILES];
__device__ int    g_num_tiles;

// ---------------- helpers ----------------
__device__ __forceinline__ void mma_f16(float* c, const uint32_t* a, const uint32_t* b) {
    asm volatile(
        "mma.sync.aligned.m16n8k16.row.col.f32.f16.f16.f32 "
        "{%0,%1,%2,%3}, {%4,%5,%6,%7}, {%8,%9}, {%0,%1,%2,%3};"
        : "+f"(c[0]), "+f"(c[1]), "+f"(c[2]), "+f"(c[3])
        : "r"(a[0]), "r"(a[1]), "r"(a[2]), "r"(a[3]),
          "r"(b[0]), "r"(b[1]));
}
__device__ __forceinline__ void ldsm_x4(uint32_t& r0, uint32_t& r1, uint32_t& r2,
                                        uint32_t& r3, uint32_t addr) {
    asm volatile("ldmatrix.sync.aligned.m8n8.x4.shared.b16 {%0,%1,%2,%3}, [%4];"
                 : "=r"(r0), "=r"(r1), "=r"(r2), "=r"(r3) : "r"(addr));
}
__device__ __forceinline__ uint32_t smem_u32(const void* p) {
    return (uint32_t)__cvta_generic_to_shared(p);
}
__device__ __forceinline__ void cp16(uint32_t dst, const void* src, int sz) {
    asm volatile("cp.async.cg.shared.global [%0], [%1], 16, %2;"
                 :: "r"(dst), "l"(src), "r"(sz));
}
__device__ __forceinline__ void cp_commit() {
    asm volatile("cp.async.commit_group;");
}
__device__ __forceinline__ void cp_wait0() {
    asm volatile("cp.async.wait_group 0;");
}
__device__ __forceinline__ void red_add_f32(float* addr, float v) {
    asm volatile("red.global.add.f32 [%0], %1;" :: "l"(addr), "f"(v) : "memory");
}

// ---------------- small kernels ----------------
// prep: zero counters + build Wr transpose [E][K] (one block, 512 threads)
__global__ void prep_kernel(const float* __restrict__ Wr) {
    int tid = threadIdx.x;
    if (tid < TOT_E) {
        g_counts[tid] = 0;
        g_cursor[tid] = 0;
    }
#pragma unroll
    for (int e = 0; e < TOT_E; e++)
        g_Wrt[e * DIN + tid] = Wr[tid * TOT_E + e];
}
__global__ void zero_out_kernel(float4* __restrict__ out) {
    int i = blockIdx.x * blockDim.x + threadIdx.x;   // over BTOK*DOUT/4
    out[i] = make_float4(0.f, 0.f, 0.f, 0.f);
}

// Router: one warp per token, float4-vectorized x and Wrt loads
__global__ void router_kernel(const float* __restrict__ x,
                              const float* __restrict__ spike,
                              const float* __restrict__ br) {
    int warp = (blockIdx.x * blockDim.x + threadIdx.x) >> 5;
    int lane = threadIdx.x & 31;
    if (warp >= BTOK) return;
    const float4* xr4 = (const float4*)(x + (size_t)warp * DIN);
    const float4* wr4 = (const float4*)g_Wrt;

    float acc[TOT_E];
#pragma unroll
    for (int e = 0; e < TOT_E; e++) acc[e] = 0.f;
#pragma unroll
    for (int i = 0; i < 4; i++) {
        int idx = i * 32 + lane;           // float4 index 0..127
        float4 xv = xr4[idx];
#pragma unroll
        for (int e = 0; e < TOT_E; e++) {
            float4 wv = wr4[e * (DIN / 4) + idx];
            acc[e] += xv.x * wv.x + xv.y * wv.y + xv.z * wv.z + xv.w * wv.w;
        }
    }
#pragma unroll
    for (int e = 0; e < TOT_E; e++)
#pragma unroll
        for (int off = 16; off; off >>= 1)
            acc[e] += __shfl_xor_sync(0xffffffffu, acc[e], off);
    float sp = (lane < TSPK) ? spike[warp * TSPK + lane] : 0.f;
#pragma unroll
    for (int off = 16; off; off >>= 1)
        sp += __shfl_xor_sync(0xffffffffu, sp, off);

    if (lane == 0) {
        float avg = sp * (1.f / TSPK);
        float lg[TOT_E];
#pragma unroll
        for (int e = 0; e < TOT_E; e++)
            lg[e] = acc[e] + br[e] + (e >= SPIKE_E0 ? avg : 0.f);
        float m = lg[0];
#pragma unroll
        for (int e = 1; e < TOT_E; e++) m = fmaxf(m, lg[e]);
        float p[TOT_E]; float Z = 0.f;
#pragma unroll
        for (int e = 0; e < TOT_E; e++) { p[e] = expf(lg[e] - m); Z += p[e]; }
        float invZ = 1.f / Z;
#pragma unroll
        for (int e = 0; e < TOT_E; e++) p[e] *= invZ;
        int e0 = 0;
#pragma unroll
        for (int e = 1; e < TOT_E; e++) if (p[e] > p[e0]) e0 = e;
        int e1 = (e0 == 0) ? 1 : 0;
#pragma unroll
        for (int e = 0; e < TOT_E; e++)
            if (e != e0 && p[e] > p[e1]) e1 = e;
        float s = p[e0] + p[e1] + 1e-9f;
        g_topk_e[2 * warp + 0] = e0;
        g_topk_e[2 * warp + 1] = e1;
        g_topk_w[2 * warp + 0] = p[e0] / s;
        g_topk_w[2 * warp + 1] = p[e1] / s;
        atomicAdd(&g_counts[e0], 1);
        atomicAdd(&g_counts[e1], 1);
    }
}

// Tile-table build only (off the spine; runs on s1 after router)
__global__ void tiles_kernel() {
    __shared__ int cnts[TOT_E];
    int tid = threadIdx.x;
    if (tid < TOT_E) cnts[tid] = g_counts[tid];
    __syncthreads();
    if (tid < TOT_E) {
        int roff = 0, toff = 0;
        for (int i = 0; i < tid; i++) {
            roff += cnts[i];
            toff += (cnts[i] + BM - 1) / BM;
        }
        int n = cnts[tid];
        for (int t = 0; t < n; t += BM) {
            g_tile_e[toff]  = tid;
            g_tile_r0[toff] = roff + t;
            int r1 = roff + t + BM;
            int re = roff + n;
            g_tile_r1[toff] = r1 < re ? r1 : re;
            toff++;
        }
        if (tid == TOT_E - 1) g_num_tiles = toff;
    }
}

// Scatter: self-sufficient (local expert prefix + zero-based cursor)
__global__ void scatter_kernel() {
    __shared__ int cnt[TOT_E];
    __shared__ int base[TOT_E];
    __shared__ int offs[TOT_E];
    int tid = threadIdx.x;
    if (tid < TOT_E) {
        cnt[tid] = 0;
        int o = 0;
        for (int i = 0; i < tid; i++) o += g_counts[i];
        offs[tid] = o;
    }
    __syncthreads();
    int i = blockIdx.x * blockDim.x + tid;
    int e = g_topk_e[i];
    int loc = atomicAdd(&cnt[e], 1);
    __syncthreads();
    if (tid < TOT_E) base[tid] = offs[tid] + atomicAdd(&g_cursor[tid], cnt[tid]);
    __syncthreads();
    int pos = base[e] + loc;
    g_perm[pos] = i >> 1;
    g_wgt[pos]  = g_topk_w[i];
}

// x (fp32) -> g_xh (half), fully coalesced
__global__ void cvtx_kernel(const float4* __restrict__ x) {
    int i = blockIdx.x * blockDim.x + threadIdx.x;
    float4 v = x[i];
    ((__half2*)g_xh)[2 * i]     = __floats2half2_rn(v.x, v.y);
    ((__half2*)g_xh)[2 * i + 1] = __floats2half2_rn(v.z, v.w);
}

// W[e][K][N] fp32 -> Wt[e][N][K] half
template<bool FIRST>
__global__ void transpose_kernel(const float* __restrict__ W, int K, int N) {
    __half* Wt = FIRST ? g_W1t : g_W2t;
    __shared__ float t[32][33];
    int e = blockIdx.z;
    const float* Ws = W + (size_t)e * K * N;
    __half* Wd = Wt + (size_t)e * K * N;
    int k0 = blockIdx.x * 32, n0 = blockIdx.y * 32;
    int tx = threadIdx.x, ty = threadIdx.y;   // 32 x 8
#pragma unroll
    for (int i = 0; i < 32; i += 8)
        t[ty + i][tx] = Ws[(size_t)(k0 + ty + i) * N + n0 + tx];
    __syncthreads();
#pragma unroll
    for (int i = 0; i < 32; i += 8)
        Wd[(size_t)(n0 + ty + i) * K + k0 + tx] = __float2half_rn(t[tx][ty + i]);
}

// ---------------- fp16 grouped GEMM: 2-stage cp.async + ldmatrix -----------
// BM=128 BN=128 BKH=32, 8 warps (2x4), warp tile 64x32, mma.m16n8k16, occ 2
template<bool FIRST>
__global__ __launch_bounds__(256, 2)
void gemm_kernel(const float* __restrict__ bias, float* __restrict__ out) {
    const int KDIM = FIRST ? DIN : DHID;
    const int NDIM = FIRST ? DHID : DOUT;
    const __half* A0 = FIRST ? g_xh : g_h;
    const __half* Bt = FIRST ? g_W1t : g_W2t;

    __shared__ __half As[2][BM][SROW];
    __shared__ __half Bs[2][BN][SROW];

    int bt = blockIdx.x;
    if (bt >= g_num_tiles) return;
    int e  = g_tile_e[bt];
    int r0 = g_tile_r0[bt];
    int r1 = g_tile_r1[bt];
    int n0 = blockIdx.y * BN;

    const __half* Bexp = Bt + (size_t)e * NDIM * KDIM;

    int tid  = threadIdx.x;
    int lane = tid & 31;
    int wid  = tid >> 5;
    int gidl = lane >> 2;
    int tg   = lane & 3;
    int wm   = (wid >> 2) * 64;
    int wn   = (wid & 3) * 32;

    // staging: 2 threads per row, each 16 halves (two 16B cp.async)
    int srow = tid >> 1;
    int scol = (tid & 1) * 16;
    int ra = r0 + srow;
    bool av = ra < r1;
    const __half* aRow;
    if (FIRST) aRow = A0 + (av ? (size_t)g_perm[ra] * KDIM : 0) + scol;
    else       aRow = A0 + (av ? (size_t)ra * KDIM : 0) + scol;
    const __half* bRow = Bexp + (size_t)(n0 + srow) * KDIM + scol;
    int asz = av ? 16 : 0;
    uint32_t aDst0 = smem_u32(&As[0][srow][scol]);
    uint32_t bDst0 = smem_u32(&Bs[0][srow][scol]);
    const uint32_t A_STAGE_B = (uint32_t)(BM * SROWB);
    const uint32_t B_STAGE_B = (uint32_t)(BN * SROWB);

    // ldmatrix lane-address bases (stage 0)
    uint32_t aLdBase = smem_u32(&As[0][0][0])
                     + (uint32_t)(wm + (lane & 15)) * SROWB
                     + (uint32_t)(lane >> 4) * 16;
    uint32_t bLdBase = smem_u32(&Bs[0][0][0])
                     + (uint32_t)(wn + (lane & 7) + ((lane >> 4) & 1) * 8) * SROWB
                     + (uint32_t)((lane >> 3) & 1) * 16;

    float acc[4][4][4];
#pragma unroll
    for (int a = 0; a < 4; a++)
#pragma unroll
        for (int b = 0; b < 4; b++)
#pragma unroll
            for (int c = 0; c < 4; c++) acc[a][b][c] = 0.f;

    const int NC = KDIM / BKH;

    // ---- prologue: stage slab 0 ----
    {
        cp16(aDst0,      aRow,     asz);
        cp16(aDst0 + 16, aRow + 8, asz);
        cp16(bDst0,      bRow,     16);
        cp16(bDst0 + 16, bRow + 8, 16);
        cp_commit();
    }

    for (int c = 0; c < NC; c++) {
        cp_wait0();
        __syncthreads();
        int cur = c & 1;

        // prefetch slab c+1
        if (c + 1 < NC) {
            int nxt = (c + 1) & 1;
            const __half* as = aRow + (c + 1) * BKH;
            const __half* bs = bRow + (c + 1) * BKH;
            uint32_t ad = aDst0 + nxt * A_STAGE_B;
            uint32_t bd = bDst0 + nxt * B_STAGE_B;
            cp16(ad,      as,     asz);
            cp16(ad + 16, as + 8, asz);
            cp16(bd,      bs,     16);
            cp16(bd + 16, bs + 8, 16);
            cp_commit();
        }

        // ---- compute slab c: two k16 steps ----
        uint32_t aB = aLdBase + (uint32_t)cur * A_STAGE_B;
        uint32_t bB = bLdBase + (uint32_t)cur * B_STAGE_B;
#pragma unroll
        for (int kk = 0; kk < 2; kk++) {
            uint32_t kB = (uint32_t)kk * 32;
            uint32_t af[4][4], bf4[2][4];
#pragma unroll
            for (int mi = 0; mi < 4; mi++)
                ldsm_x4(af[mi][0], af[mi][1], af[mi][2], af[mi][3],
                        aB + kB + (uint32_t)mi * (16 * SROWB));
#pragma unroll
            for (int nj = 0; nj < 2; nj++)
                ldsm_x4(bf4[nj][0], bf4[nj][1], bf4[nj][2], bf4[nj][3],
                        bB + kB + (uint32_t)nj * (16 * SROWB));
#pragma unroll
            for (int mi = 0; mi < 4; mi++)
#pragma unroll
                for (int ni = 0; ni < 4; ni++)
                    mma_f16(acc[mi][ni], af[mi], &bf4[ni >> 1][(ni & 1) * 2]);
        }
        __syncthreads();
    }

    // ---- epilogue ----
    const float* be = bias + (size_t)e * NDIM;
#pragma unroll
    for (int mi = 0; mi < 4; mi++) {
#pragma unroll
        for (int ri = 0; ri < 2; ri++) {
            int r = r0 + wm + mi * 16 + gidl + ri * 8;
            if (r >= r1) continue;
            if (FIRST) {
#pragma unroll
                for (int ni = 0; ni < 4; ni++) {
                    int cc = n0 + wn + ni * 8 + 2 * tg;
                    float v0 = fmaxf(acc[mi][ni][ri * 2 + 0] + be[cc],     0.f);
                    float v1 = fmaxf(acc[mi][ni][ri * 2 + 1] + be[cc + 1], 0.f);
                    *reinterpret_cast<__half2*>(g_h + (size_t)r * NDIM + cc) =
                        __floats2half2_rn(v0, v1);
                }
            } else {
                float sc = g_wgt[r];
                int token = g_perm[r];
                float* orow = out + (size_t)token * NDIM;
#pragma unroll
                for (int ni = 0; ni < 4; ni++) {
                    int cc = n0 + wn + ni * 8 + 2 * tg;
                    float v0 = (acc[mi][ni][ri * 2 + 0] + be[cc])     * sc;
                    float v1 = (acc[mi][ni][ri * 2 + 1] + be[cc + 1]) * sc;
                    red_add_f32(orow + cc,     v0);
                    red_add_f32(orow + cc + 1, v1);
                }
            }
        }
    }
}

// ---------------- launch: multi-stream DAG (capture-safe fork/join) -------
extern "C" void kernel_launch(void* const* d_in, const int* in_sizes, int n_in,
                              void* d_out, int out_size) {
    const float* x     = (const float*)d_in[0];
    const float* spike = (const float*)d_in[1];
    const float* Wr    = (const float*)d_in[2];
    const float* br    = (const float*)d_in[3];
    const float* W1    = (const float*)d_in[4];
    const float* b1    = (const float*)d_in[5];
    const float* W2    = (const float*)d_in[6];
    const float* b2    = (const float*)d_in[7];
    float* out = (float*)d_out;

    static cudaStream_t s1 = nullptr, s2 = nullptr;
    static cudaEvent_t evFork = nullptr, evR = nullptr, evA = nullptr, evB = nullptr;
    if (s1 == nullptr) {
        cudaStreamCreateWithFlags(&s1, cudaStreamNonBlocking);
        cudaStreamCreateWithFlags(&s2, cudaStreamNonBlocking);
        cudaEventCreateWithFlags(&evFork, cudaEventDisableTiming);
        cudaEventCreateWithFlags(&evR, cudaEventDisableTiming);
        cudaEventCreateWithFlags(&evA, cudaEventDisableTiming);
        cudaEventCreateWithFlags(&evB, cudaEventDisableTiming);
    }

    // fork
    cudaEventRecord(evFork, 0);
    cudaStreamWaitEvent(s1, evFork, 0);
    cudaStreamWaitEvent(s2, evFork, 0);

    // s2: inputs GEMM2 needs (W2 transpose, output zero-fill)
    transpose_kernel<false><<<dim3(DHID / 32, DOUT / 32, TOT_E), dim3(32, 8), 0, s2>>>(W2, DHID, DOUT);
    zero_out_kernel<<<(BTOK * DOUT / 4) / 256, 256, 0, s2>>>((float4*)out);
    cudaEventRecord(evB, s2);

    // main spine: prep (counters + Wr transpose) -> router -> scatter
    prep_kernel<<<1, DIN>>>(Wr);
    router_kernel<<<BTOK / 8, 256>>>(x, spike, br);
    cudaEventRecord(evR, 0);
    scatter_kernel<<<NPAIRS / 256, 256>>>();

    // s1: inputs GEMM1 needs (x->half, W1 transpose, tile table after router)
    cvtx_kernel<<<(BTOK * DIN / 4) / 256, 256, 0, s1>>>((const float4*)x);
    transpose_kernel<true><<<dim3(DIN / 32, DHID / 32, TOT_E), dim3(32, 8), 0, s1>>>(W1, DIN, DHID);
    cudaStreamWaitEvent(s1, evR, 0);
    tiles_kernel<<<1, 32, 0, s1>>>();
    cudaEventRecord(evA, s1);

    // join s1 -> GEMM1
    cudaStreamWaitEvent(0, evA, 0);
    gemm_kernel<true><<<dim3(MAX_TILES, DHID / BN), 256>>>(b1, nullptr);

    // join s2 -> GEMM2 (fused combine via red.global.add into out)
    cudaStreamWaitEvent(0, evB, 0);
    gemm_kernel<false><<<dim3(MAX_TILES, DOUT / BN), 256>>>(b2, out);
}